// round 6
// baseline (speedup 1.0000x reference)
#include <cuda_runtime.h>
#include <cuda_bf16.h>
#include <cstdint>

// GCN layer: out = segment_sum(val * x[col]) @ W^T + b
//  = b + segment_sum(val * (x @ W^T)[col])    (projection commutes with sum)
//
// K1: xW = x @ W^T via mma.sync tf32 m16n8k8 (fp32 accum).
// K2: SpMM, warp-per-node. 8-edge unroll with all 8 gathers issued before any
//     FMA (forces high reg count -> real MLP=8), dual accumulators.

#define D 128
#define MAX_N 50000
#define SPAD 132            // 128 + 4 padding words -> conflict-free frag loads

__device__ float g_xW[MAX_N * D];

__device__ __forceinline__ float to_tf32(float f) {
    float r;
    asm("cvt.rna.tf32.f32 %0, %1;" : "=f"(r) : "f"(f));
    return r;
}

__device__ __forceinline__ void mma_tf32(float* d, const uint32_t* a, const uint32_t* b) {
    asm volatile(
        "mma.sync.aligned.m16n8k8.row.col.f32.tf32.tf32.f32 "
        "{%0,%1,%2,%3}, {%4,%5,%6,%7}, {%8,%9}, {%0,%1,%2,%3};"
        : "+f"(d[0]), "+f"(d[1]), "+f"(d[2]), "+f"(d[3])
        : "r"(a[0]), "r"(a[1]), "r"(a[2]), "r"(a[3]), "r"(b[0]), "r"(b[1]));
}

// ---------------------------------------------------------------------------
// K1: xW[i, o] = sum_k x[i,k] * W[o,k]
// 128x128 tile per CTA, 256 threads = 8 warps (4x2), warp tile 32x64.
// ---------------------------------------------------------------------------
__global__ __launch_bounds__(256, 1)
void gemm_xw_mma(const float* __restrict__ x, const float* __restrict__ W, int N) {
    extern __shared__ float smem[];
    float* As = smem;                 // [128][SPAD]
    float* Ws = smem + 128 * SPAD;    // [128][SPAD]

    const int tid = threadIdx.x;
    const int block_row = blockIdx.x * 128;

    #pragma unroll
    for (int it = 0; it < 16; it++) {
        const int slot = tid + it * 256;        // float4 slot, 4096 total
        const int r = slot >> 5;
        const int c = (slot & 31) * 4;
        const int gr = block_row + r;
        float4 v = make_float4(0.f, 0.f, 0.f, 0.f);
        if (gr < N) v = *reinterpret_cast<const float4*>(x + (size_t)gr * D + c);
        float* dst = As + r * SPAD + c;
        dst[0] = to_tf32(v.x); dst[1] = to_tf32(v.y);
        dst[2] = to_tf32(v.z); dst[3] = to_tf32(v.w);
    }
    #pragma unroll
    for (int it = 0; it < 16; it++) {
        const int slot = tid + it * 256;
        const int r = slot >> 5;
        const int c = (slot & 31) * 4;
        float4 v = *reinterpret_cast<const float4*>(W + (size_t)r * D + c);
        float* dst = Ws + r * SPAD + c;
        dst[0] = to_tf32(v.x); dst[1] = to_tf32(v.y);
        dst[2] = to_tf32(v.z); dst[3] = to_tf32(v.w);
    }
    __syncthreads();

    const uint32_t* Ab = reinterpret_cast<const uint32_t*>(As);
    const uint32_t* Wb = reinterpret_cast<const uint32_t*>(Ws);

    const int wid  = tid >> 5;
    const int lane = tid & 31;
    const int grp  = lane >> 2;       // 0..7
    const int tig  = lane & 3;        // 0..3
    const int warpRow = (wid & 3) * 32;
    const int warpCol = (wid >> 2) * 64;

    float acc[2][8][4];
    #pragma unroll
    for (int mt = 0; mt < 2; mt++)
        #pragma unroll
        for (int nt = 0; nt < 8; nt++)
            #pragma unroll
            for (int q = 0; q < 4; q++) acc[mt][nt][q] = 0.f;

    #pragma unroll
    for (int ks = 0; ks < 16; ks++) {
        const int k0 = ks * 8;
        uint32_t a[2][4];
        #pragma unroll
        for (int mt = 0; mt < 2; mt++) {
            const int r0 = warpRow + mt * 16 + grp;
            a[mt][0] = Ab[r0 * SPAD + k0 + tig];
            a[mt][1] = Ab[(r0 + 8) * SPAD + k0 + tig];
            a[mt][2] = Ab[r0 * SPAD + k0 + tig + 4];
            a[mt][3] = Ab[(r0 + 8) * SPAD + k0 + tig + 4];
        }
        uint32_t b[8][2];
        #pragma unroll
        for (int nt = 0; nt < 8; nt++) {
            const int n0 = warpCol + nt * 8 + grp;
            b[nt][0] = Wb[n0 * SPAD + k0 + tig];
            b[nt][1] = Wb[n0 * SPAD + k0 + tig + 4];
        }
        #pragma unroll
        for (int mt = 0; mt < 2; mt++)
            #pragma unroll
            for (int nt = 0; nt < 8; nt++)
                mma_tf32(acc[mt][nt], a[mt], b[nt]);
    }

    #pragma unroll
    for (int mt = 0; mt < 2; mt++) {
        const int r0 = block_row + warpRow + mt * 16 + grp;
        #pragma unroll
        for (int nt = 0; nt < 8; nt++) {
            const int c0 = warpCol + nt * 8 + tig * 2;
            if (r0 < N)
                *reinterpret_cast<float2*>(g_xW + (size_t)r0 * D + c0) =
                    make_float2(acc[mt][nt][0], acc[mt][nt][1]);
            if (r0 + 8 < N)
                *reinterpret_cast<float2*>(g_xW + (size_t)(r0 + 8) * D + c0) =
                    make_float2(acc[mt][nt][2], acc[mt][nt][3]);
        }
    }
}

// ---------------------------------------------------------------------------
// K2: out[i] = b + sum_{e in [rp(i), rp(i+1))} val[e] * xW[col[e]]
// rp(j) = lower_bound(edge_row, j), computed by lanes 0/1 + shfl.
// ---------------------------------------------------------------------------
#define FMA4(ACC, V, A) \
    do { ACC.x = fmaf(V, A.x, ACC.x); ACC.y = fmaf(V, A.y, ACC.y); \
         ACC.z = fmaf(V, A.z, ACC.z); ACC.w = fmaf(V, A.w, ACC.w); } while (0)

__global__ void
spmm_kernel(const int* __restrict__ erow, const int* __restrict__ ecol,
            const float* __restrict__ eval, const float* __restrict__ b,
            float* __restrict__ out, int N, int E) {
    const int warp = (blockIdx.x * blockDim.x + threadIdx.x) >> 5;
    const int lane = threadIdx.x & 31;
    if (warp >= N) return;

    int bound = 0;
    if (lane < 2) {
        const int tgt = warp + lane;   // lower_bound target
        int lo = 0, hi = E;
        while (lo < hi) {
            int mid = (lo + hi) >> 1;
            if (__ldg(erow + mid) < tgt) lo = mid + 1; else hi = mid;
        }
        bound = lo;
    }
    const int start = __shfl_sync(0xFFFFFFFFu, bound, 0);
    const int end   = __shfl_sync(0xFFFFFFFFu, bound, 1);

    const float* xw = g_xW + lane * 4;     // lane's 4-dim slice base

    float4 acc0 = *reinterpret_cast<const float4*>(b + lane * 4);
    float4 acc1 = make_float4(0.f, 0.f, 0.f, 0.f);

    int e = start;
    while (e < end && (e & 3)) {           // peel to 4-alignment
        float4 a = *reinterpret_cast<const float4*>(xw + (size_t)__ldg(ecol + e) * D);
        float  v = __ldg(eval + e);
        FMA4(acc0, v, a);
        e++;
    }
    // main: 8 edges per iteration, all 8 gathers issued before any FMA
    for (; e + 8 <= end; e += 8) {
        const int4   c0 = __ldg(reinterpret_cast<const int4*>(ecol + e));
        const int4   c1 = __ldg(reinterpret_cast<const int4*>(ecol + e + 4));
        const float4 v0 = __ldg(reinterpret_cast<const float4*>(eval + e));
        const float4 v1 = __ldg(reinterpret_cast<const float4*>(eval + e + 4));
        const float4 a0 = *reinterpret_cast<const float4*>(xw + (size_t)c0.x * D);
        const float4 a1 = *reinterpret_cast<const float4*>(xw + (size_t)c0.y * D);
        const float4 a2 = *reinterpret_cast<const float4*>(xw + (size_t)c0.z * D);
        const float4 a3 = *reinterpret_cast<const float4*>(xw + (size_t)c0.w * D);
        const float4 a4 = *reinterpret_cast<const float4*>(xw + (size_t)c1.x * D);
        const float4 a5 = *reinterpret_cast<const float4*>(xw + (size_t)c1.y * D);
        const float4 a6 = *reinterpret_cast<const float4*>(xw + (size_t)c1.z * D);
        const float4 a7 = *reinterpret_cast<const float4*>(xw + (size_t)c1.w * D);
        FMA4(acc0, v0.x, a0); FMA4(acc1, v0.y, a1);
        FMA4(acc0, v0.z, a2); FMA4(acc1, v0.w, a3);
        FMA4(acc0, v1.x, a4); FMA4(acc1, v1.y, a5);
        FMA4(acc0, v1.z, a6); FMA4(acc1, v1.w, a7);
    }
    // 4-edge step
    for (; e + 4 <= end; e += 4) {
        const int4   c0 = __ldg(reinterpret_cast<const int4*>(ecol + e));
        const float4 v0 = __ldg(reinterpret_cast<const float4*>(eval + e));
        const float4 a0 = *reinterpret_cast<const float4*>(xw + (size_t)c0.x * D);
        const float4 a1 = *reinterpret_cast<const float4*>(xw + (size_t)c0.y * D);
        const float4 a2 = *reinterpret_cast<const float4*>(xw + (size_t)c0.z * D);
        const float4 a3 = *reinterpret_cast<const float4*>(xw + (size_t)c0.w * D);
        FMA4(acc0, v0.x, a0); FMA4(acc1, v0.y, a1);
        FMA4(acc0, v0.z, a2); FMA4(acc1, v0.w, a3);
    }
    // tail
    while (e < end) {
        float4 a = *reinterpret_cast<const float4*>(xw + (size_t)__ldg(ecol + e) * D);
        float  v = __ldg(eval + e);
        FMA4(acc0, v, a);
        e++;
    }

    acc0.x += acc1.x; acc0.y += acc1.y; acc0.z += acc1.z; acc0.w += acc1.w;
    *reinterpret_cast<float4*>(out + (size_t)warp * D + lane * 4) = acc0;
}

// ---------------------------------------------------------------------------
extern "C" void kernel_launch(void* const* d_in, const int* in_sizes, int n_in,
                              void* d_out, int out_size) {
    const float* x    = (const float*)d_in[0];
    const int*   erow = (const int*)  d_in[1];
    const int*   ecol = (const int*)  d_in[2];
    const float* eval = (const float*)d_in[3];
    const float* W    = (const float*)d_in[4];
    const float* b    = (const float*)d_in[5];

    const int N = in_sizes[0] / D;
    const int E = in_sizes[1];

    const int smem_bytes = 2 * 128 * SPAD * sizeof(float);   // ~135 KB
    cudaFuncSetAttribute(gemm_xw_mma, cudaFuncAttributeMaxDynamicSharedMemorySize, smem_bytes);

    gemm_xw_mma<<<(N + 127) / 128, 256, smem_bytes>>>(x, W, N);

    const int warps_per_block = 8;
    spmm_kernel<<<(N + warps_per_block - 1) / warps_per_block, warps_per_block * 32>>>(
        erow, ecol, eval, b, (float*)d_out, N, E);
}

// round 8
// speedup vs baseline: 1.1995x; 1.1995x over previous
#include <cuda_runtime.h>
#include <cuda_bf16.h>
#include <cstdint>

// GCN layer: out = segment_sum(val * x[col]) @ W^T + b
//  = b + segment_sum(val * (x @ W^T)[col])    (projection commutes with sum)
//
// K1: rowptr[i] = lower_bound(edge_row, i)  (edge_row sorted; massively parallel)
// K2: xW = x @ W^T via mma.sync tf32 m16n8k8 (fp32 accum)
// K3: SpMM: 2 warps per node (each owns 64 dims, float2/lane), 4-edge batches.

#define D 128
#define MAX_N 50000
#define SPAD 132            // 128 + 4 padding words -> conflict-free frag loads

__device__ float g_xW[MAX_N * D];
__device__ int   g_rowptr[MAX_N + 1];

__device__ __forceinline__ float to_tf32(float f) {
    float r;
    asm("cvt.rna.tf32.f32 %0, %1;" : "=f"(r) : "f"(f));
    return r;
}

__device__ __forceinline__ void mma_tf32(float* d, const uint32_t* a, const uint32_t* b) {
    asm volatile(
        "mma.sync.aligned.m16n8k8.row.col.f32.tf32.tf32.f32 "
        "{%0,%1,%2,%3}, {%4,%5,%6,%7}, {%8,%9}, {%0,%1,%2,%3};"
        : "+f"(d[0]), "+f"(d[1]), "+f"(d[2]), "+f"(d[3])
        : "r"(a[0]), "r"(a[1]), "r"(a[2]), "r"(a[3]), "r"(b[0]), "r"(b[1]));
}

// ---------------------------------------------------------------------------
// K1: CSR offsets from sorted edge_row.
// ---------------------------------------------------------------------------
__global__ void build_rowptr_kernel(const int* __restrict__ rows, int E, int N) {
    int i = blockIdx.x * blockDim.x + threadIdx.x;
    if (i > N) return;
    int lo = 0, hi = E;
    while (lo < hi) {
        int mid = (lo + hi) >> 1;
        if (__ldg(rows + mid) < i) lo = mid + 1; else hi = mid;
    }
    g_rowptr[i] = lo;
}

// ---------------------------------------------------------------------------
// K2: xW[i, o] = sum_k x[i,k] * W[o,k]
// 128x128 tile per CTA, 256 threads = 8 warps (4x2), warp tile 32x64.
// ---------------------------------------------------------------------------
__global__ __launch_bounds__(256, 1)
void gemm_xw_mma(const float* __restrict__ x, const float* __restrict__ W, int N) {
    extern __shared__ float smem[];
    float* As = smem;                 // [128][SPAD]
    float* Ws = smem + 128 * SPAD;    // [128][SPAD]

    const int tid = threadIdx.x;
    const int block_row = blockIdx.x * 128;

    #pragma unroll
    for (int it = 0; it < 16; it++) {
        const int slot = tid + it * 256;        // float4 slot, 4096 total
        const int r = slot >> 5;
        const int c = (slot & 31) * 4;
        const int gr = block_row + r;
        float4 v = make_float4(0.f, 0.f, 0.f, 0.f);
        if (gr < N) v = *reinterpret_cast<const float4*>(x + (size_t)gr * D + c);
        float* dst = As + r * SPAD + c;
        dst[0] = to_tf32(v.x); dst[1] = to_tf32(v.y);
        dst[2] = to_tf32(v.z); dst[3] = to_tf32(v.w);
    }
    #pragma unroll
    for (int it = 0; it < 16; it++) {
        const int slot = tid + it * 256;
        const int r = slot >> 5;
        const int c = (slot & 31) * 4;
        float4 v = *reinterpret_cast<const float4*>(W + (size_t)r * D + c);
        float* dst = Ws + r * SPAD + c;
        dst[0] = to_tf32(v.x); dst[1] = to_tf32(v.y);
        dst[2] = to_tf32(v.z); dst[3] = to_tf32(v.w);
    }
    __syncthreads();

    const uint32_t* Ab = reinterpret_cast<const uint32_t*>(As);
    const uint32_t* Wb = reinterpret_cast<const uint32_t*>(Ws);

    const int wid  = tid >> 5;
    const int lane = tid & 31;
    const int grp  = lane >> 2;       // 0..7
    const int tig  = lane & 3;        // 0..3
    const int warpRow = (wid & 3) * 32;
    const int warpCol = (wid >> 2) * 64;

    float acc[2][8][4];
    #pragma unroll
    for (int mt = 0; mt < 2; mt++)
        #pragma unroll
        for (int nt = 0; nt < 8; nt++)
            #pragma unroll
            for (int q = 0; q < 4; q++) acc[mt][nt][q] = 0.f;

    #pragma unroll
    for (int ks = 0; ks < 16; ks++) {
        const int k0 = ks * 8;
        uint32_t a[2][4];
        #pragma unroll
        for (int mt = 0; mt < 2; mt++) {
            const int r0 = warpRow + mt * 16 + grp;
            a[mt][0] = Ab[r0 * SPAD + k0 + tig];
            a[mt][1] = Ab[(r0 + 8) * SPAD + k0 + tig];
            a[mt][2] = Ab[r0 * SPAD + k0 + tig + 4];
            a[mt][3] = Ab[(r0 + 8) * SPAD + k0 + tig + 4];
        }
        uint32_t b[8][2];
        #pragma unroll
        for (int nt = 0; nt < 8; nt++) {
            const int n0 = warpCol + nt * 8 + grp;
            b[nt][0] = Wb[n0 * SPAD + k0 + tig];
            b[nt][1] = Wb[n0 * SPAD + k0 + tig + 4];
        }
        #pragma unroll
        for (int mt = 0; mt < 2; mt++)
            #pragma unroll
            for (int nt = 0; nt < 8; nt++)
                mma_tf32(acc[mt][nt], a[mt], b[nt]);
    }

    #pragma unroll
    for (int mt = 0; mt < 2; mt++) {
        const int r0 = block_row + warpRow + mt * 16 + grp;
        #pragma unroll
        for (int nt = 0; nt < 8; nt++) {
            const int c0 = warpCol + nt * 8 + tig * 2;
            if (r0 < N)
                *reinterpret_cast<float2*>(g_xW + (size_t)r0 * D + c0) =
                    make_float2(acc[mt][nt][0], acc[mt][nt][1]);
            if (r0 + 8 < N)
                *reinterpret_cast<float2*>(g_xW + (size_t)(r0 + 8) * D + c0) =
                    make_float2(acc[mt][nt][2], acc[mt][nt][3]);
        }
    }
}

// ---------------------------------------------------------------------------
// K3: out[i] = b + sum_{e in [rp[i], rp[i+1])} val[e] * xW[col[e]]
// 2 warps per node: warp half h owns dims [h*64, h*64+64), float2 per lane.
// 4-edge batches: 4 independent LDG.64 gathers in flight, dual accumulators.
// ---------------------------------------------------------------------------
#define FMA2(ACC, V, A) \
    do { ACC.x = fmaf(V, A.x, ACC.x); ACC.y = fmaf(V, A.y, ACC.y); } while (0)

__global__ __launch_bounds__(256)
void spmm_kernel(const int* __restrict__ ecol, const float* __restrict__ eval,
                 const float* __restrict__ b, float* __restrict__ out, int N) {
    const int gwarp = (blockIdx.x * blockDim.x + threadIdx.x) >> 5;
    const int node  = gwarp >> 1;
    const int half  = gwarp & 1;
    const int lane  = threadIdx.x & 31;
    if (node >= N) return;

    const int start = g_rowptr[node];
    const int end   = g_rowptr[node + 1];

    const int dim = half * 64 + lane * 2;
    const float* xw = g_xW + dim;

    float2 acc0 = *reinterpret_cast<const float2*>(b + dim);
    float2 acc1 = make_float2(0.f, 0.f);

    int e = start;
    while (e < end && (e & 3)) {           // peel to 4-alignment
        float2 a = *reinterpret_cast<const float2*>(xw + (size_t)__ldg(ecol + e) * D);
        FMA2(acc0, __ldg(eval + e), a);
        e++;
    }
    for (; e + 4 <= end; e += 4) {         // main: 4 edges, 4 gathers in flight
        const int4   c = __ldg(reinterpret_cast<const int4*>(ecol + e));
        const float4 v = __ldg(reinterpret_cast<const float4*>(eval + e));
        const float2 a0 = *reinterpret_cast<const float2*>(xw + (size_t)c.x * D);
        const float2 a1 = *reinterpret_cast<const float2*>(xw + (size_t)c.y * D);
        const float2 a2 = *reinterpret_cast<const float2*>(xw + (size_t)c.z * D);
        const float2 a3 = *reinterpret_cast<const float2*>(xw + (size_t)c.w * D);
        FMA2(acc0, v.x, a0); FMA2(acc1, v.y, a1);
        FMA2(acc0, v.z, a2); FMA2(acc1, v.w, a3);
    }
    while (e < end) {                      // tail
        float2 a = *reinterpret_cast<const float2*>(xw + (size_t)__ldg(ecol + e) * D);
        FMA2(acc0, __ldg(eval + e), a);
        e++;
    }

    acc0.x += acc1.x; acc0.y += acc1.y;
    *reinterpret_cast<float2*>(out + (size_t)node * D + dim) = acc0;
}

// ---------------------------------------------------------------------------
extern "C" void kernel_launch(void* const* d_in, const int* in_sizes, int n_in,
                              void* d_out, int out_size) {
    const float* x    = (const float*)d_in[0];
    const int*   erow = (const int*)  d_in[1];
    const int*   ecol = (const int*)  d_in[2];
    const float* eval = (const float*)d_in[3];
    const float* W    = (const float*)d_in[4];
    const float* b    = (const float*)d_in[5];

    const int N = in_sizes[0] / D;
    const int E = in_sizes[1];

    const int smem_bytes = 2 * 128 * SPAD * sizeof(float);   // ~135 KB
    cudaFuncSetAttribute(gemm_xw_mma, cudaFuncAttributeMaxDynamicSharedMemorySize, smem_bytes);

    build_rowptr_kernel<<<(N + 1 + 255) / 256, 256>>>(erow, E, N);
    gemm_xw_mma<<<(N + 127) / 128, 256, smem_bytes>>>(x, W, N);

    const int total_warps = 2 * N;                 // 2 warps per node
    spmm_kernel<<<(total_warps * 32 + 255) / 256, 256>>>(ecol, eval, b, (float*)d_out, N);
}

// round 9
// speedup vs baseline: 1.3394x; 1.1166x over previous
#include <cuda_runtime.h>
#include <cuda_bf16.h>
#include <cstdint>

// GCN layer: out = segment_sum(val * x[col]) @ W^T + b
//  = b + segment_sum(val * (x @ W^T)[col])    (projection commutes with sum)
//
// K1: rowptr via one-pass boundary detection over sorted edge_row (no search).
// K2: xW = x @ W^T via mma.sync tf32 m16n8k8 (fp32 accum).
// K3: SpMM: 2 warps per node (each owns 64 dims, float2/lane), 4-edge batches.

#define D 128
#define MAX_N 50000
#define SPAD 132            // 128 + 4 padding words -> conflict-free frag loads

__device__ float g_xW[MAX_N * D];
__device__ int   g_rowptr[MAX_N + 1];

__device__ __forceinline__ float to_tf32(float f) {
    float r;
    asm("cvt.rna.tf32.f32 %0, %1;" : "=f"(r) : "f"(f));
    return r;
}

__device__ __forceinline__ void mma_tf32(float* d, const uint32_t* a, const uint32_t* b) {
    asm volatile(
        "mma.sync.aligned.m16n8k8.row.col.f32.tf32.tf32.f32 "
        "{%0,%1,%2,%3}, {%4,%5,%6,%7}, {%8,%9}, {%0,%1,%2,%3};"
        : "+f"(d[0]), "+f"(d[1]), "+f"(d[2]), "+f"(d[3])
        : "r"(a[0]), "r"(a[1]), "r"(a[2]), "r"(a[3]), "r"(b[0]), "r"(b[1]));
}

// ---------------------------------------------------------------------------
// K1: CSR offsets from sorted edge_row, one coalesced pass.
// rowptr[i] = lower_bound(rows, i): for i in (rows[e-1], rows[e]] -> e.
// ---------------------------------------------------------------------------
__global__ void rowptr_from_sorted(const int* __restrict__ rows, int E, int N) {
    const int e = blockIdx.x * blockDim.x + threadIdx.x;
    if (e >= E) return;
    const int cur  = __ldg(rows + e);
    const int prev = (e == 0) ? -1 : __ldg(rows + e - 1);
    for (int r = prev; r < cur; r++) g_rowptr[r + 1] = e;
    if (e == 0) g_rowptr[0] = 0;
    if (e == E - 1)
        for (int r = cur; r < N; r++) g_rowptr[r + 1] = E;
}

// ---------------------------------------------------------------------------
// K2: xW[i, o] = sum_k x[i,k] * W[o,k]
// 128x128 tile per CTA, 256 threads = 8 warps (4x2), warp tile 32x64.
// ---------------------------------------------------------------------------
__global__ __launch_bounds__(256, 1)
void gemm_xw_mma(const float* __restrict__ x, const float* __restrict__ W, int N) {
    extern __shared__ float smem[];
    float* As = smem;                 // [128][SPAD]
    float* Ws = smem + 128 * SPAD;    // [128][SPAD]

    const int tid = threadIdx.x;
    const int block_row = blockIdx.x * 128;

    #pragma unroll
    for (int it = 0; it < 16; it++) {
        const int slot = tid + it * 256;        // float4 slot, 4096 total
        const int r = slot >> 5;
        const int c = (slot & 31) * 4;
        const int gr = block_row + r;
        float4 v = make_float4(0.f, 0.f, 0.f, 0.f);
        if (gr < N) v = *reinterpret_cast<const float4*>(x + (size_t)gr * D + c);
        float* dst = As + r * SPAD + c;
        dst[0] = to_tf32(v.x); dst[1] = to_tf32(v.y);
        dst[2] = to_tf32(v.z); dst[3] = to_tf32(v.w);
    }
    #pragma unroll
    for (int it = 0; it < 16; it++) {
        const int slot = tid + it * 256;
        const int r = slot >> 5;
        const int c = (slot & 31) * 4;
        float4 v = *reinterpret_cast<const float4*>(W + (size_t)r * D + c);
        float* dst = Ws + r * SPAD + c;
        dst[0] = to_tf32(v.x); dst[1] = to_tf32(v.y);
        dst[2] = to_tf32(v.z); dst[3] = to_tf32(v.w);
    }
    __syncthreads();

    const uint32_t* Ab = reinterpret_cast<const uint32_t*>(As);
    const uint32_t* Wb = reinterpret_cast<const uint32_t*>(Ws);

    const int wid  = tid >> 5;
    const int lane = tid & 31;
    const int grp  = lane >> 2;       // 0..7
    const int tig  = lane & 3;        // 0..3
    const int warpRow = (wid & 3) * 32;
    const int warpCol = (wid >> 2) * 64;

    float acc[2][8][4];
    #pragma unroll
    for (int mt = 0; mt < 2; mt++)
        #pragma unroll
        for (int nt = 0; nt < 8; nt++)
            #pragma unroll
            for (int q = 0; q < 4; q++) acc[mt][nt][q] = 0.f;

    #pragma unroll
    for (int ks = 0; ks < 16; ks++) {
        const int k0 = ks * 8;
        uint32_t a[2][4];
        #pragma unroll
        for (int mt = 0; mt < 2; mt++) {
            const int r0 = warpRow + mt * 16 + grp;
            a[mt][0] = Ab[r0 * SPAD + k0 + tig];
            a[mt][1] = Ab[(r0 + 8) * SPAD + k0 + tig];
            a[mt][2] = Ab[r0 * SPAD + k0 + tig + 4];
            a[mt][3] = Ab[(r0 + 8) * SPAD + k0 + tig + 4];
        }
        uint32_t b[8][2];
        #pragma unroll
        for (int nt = 0; nt < 8; nt++) {
            const int n0 = warpCol + nt * 8 + grp;
            b[nt][0] = Wb[n0 * SPAD + k0 + tig];
            b[nt][1] = Wb[n0 * SPAD + k0 + tig + 4];
        }
        #pragma unroll
        for (int mt = 0; mt < 2; mt++)
            #pragma unroll
            for (int nt = 0; nt < 8; nt++)
                mma_tf32(acc[mt][nt], a[mt], b[nt]);
    }

    #pragma unroll
    for (int mt = 0; mt < 2; mt++) {
        const int r0 = block_row + warpRow + mt * 16 + grp;
        #pragma unroll
        for (int nt = 0; nt < 8; nt++) {
            const int c0 = warpCol + nt * 8 + tig * 2;
            if (r0 < N)
                *reinterpret_cast<float2*>(g_xW + (size_t)r0 * D + c0) =
                    make_float2(acc[mt][nt][0], acc[mt][nt][1]);
            if (r0 + 8 < N)
                *reinterpret_cast<float2*>(g_xW + (size_t)(r0 + 8) * D + c0) =
                    make_float2(acc[mt][nt][2], acc[mt][nt][3]);
        }
    }
}

// ---------------------------------------------------------------------------
// K3: out[i] = b + sum_{e in [rp[i], rp[i+1])} val[e] * xW[col[e]]
// 2 warps per node: warp half h owns dims [h*64, h*64+64), float2 per lane.
// ---------------------------------------------------------------------------
#define FMA2(ACC, V, A) \
    do { ACC.x = fmaf(V, A.x, ACC.x); ACC.y = fmaf(V, A.y, ACC.y); } while (0)

__global__ __launch_bounds__(256)
void spmm_kernel(const int* __restrict__ ecol, const float* __restrict__ eval,
                 const float* __restrict__ b, float* __restrict__ out, int N) {
    const int gwarp = (blockIdx.x * blockDim.x + threadIdx.x) >> 5;
    const int node  = gwarp >> 1;
    const int half  = gwarp & 1;
    const int lane  = threadIdx.x & 31;
    if (node >= N) return;

    const int start = g_rowptr[node];
    const int end   = g_rowptr[node + 1];

    const int dim = half * 64 + lane * 2;
    const float* xw = g_xW + dim;

    float2 acc0 = *reinterpret_cast<const float2*>(b + dim);
    float2 acc1 = make_float2(0.f, 0.f);

    int e = start;
    while (e < end && (e & 3)) {           // peel to 4-alignment
        float2 a = *reinterpret_cast<const float2*>(xw + (size_t)__ldg(ecol + e) * D);
        FMA2(acc0, __ldg(eval + e), a);
        e++;
    }
    for (; e + 4 <= end; e += 4) {         // main: 4 edges, 4 gathers in flight
        const int4   c = __ldg(reinterpret_cast<const int4*>(ecol + e));
        const float4 v = __ldg(reinterpret_cast<const float4*>(eval + e));
        const float2 a0 = *reinterpret_cast<const float2*>(xw + (size_t)c.x * D);
        const float2 a1 = *reinterpret_cast<const float2*>(xw + (size_t)c.y * D);
        const float2 a2 = *reinterpret_cast<const float2*>(xw + (size_t)c.z * D);
        const float2 a3 = *reinterpret_cast<const float2*>(xw + (size_t)c.w * D);
        FMA2(acc0, v.x, a0); FMA2(acc1, v.y, a1);
        FMA2(acc0, v.z, a2); FMA2(acc1, v.w, a3);
    }
    while (e < end) {                      // tail
        float2 a = *reinterpret_cast<const float2*>(xw + (size_t)__ldg(ecol + e) * D);
        FMA2(acc0, __ldg(eval + e), a);
        e++;
    }

    acc0.x += acc1.x; acc0.y += acc1.y;
    *reinterpret_cast<float2*>(out + (size_t)node * D + dim) = acc0;
}

// ---------------------------------------------------------------------------
extern "C" void kernel_launch(void* const* d_in, const int* in_sizes, int n_in,
                              void* d_out, int out_size) {
    const float* x    = (const float*)d_in[0];
    const int*   erow = (const int*)  d_in[1];
    const int*   ecol = (const int*)  d_in[2];
    const float* eval = (const float*)d_in[3];
    const float* W    = (const float*)d_in[4];
    const float* b    = (const float*)d_in[5];

    const int N = in_sizes[0] / D;
    const int E = in_sizes[1];

    const int smem_bytes = 2 * 128 * SPAD * sizeof(float);   // ~135 KB
    cudaFuncSetAttribute(gemm_xw_mma, cudaFuncAttributeMaxDynamicSharedMemorySize, smem_bytes);

    rowptr_from_sorted<<<(E + 255) / 256, 256>>>(erow, E, N);
    gemm_xw_mma<<<(N + 127) / 128, 256, smem_bytes>>>(x, W, N);

    const int total_warps = 2 * N;                 // 2 warps per node
    spmm_kernel<<<(total_warps * 32 + 255) / 256, 256>>>(ecol, eval, b, (float*)d_out, N);
}